// round 15
// baseline (speedup 1.0000x reference)
#include <cuda_runtime.h>
#include <cuda_bf16.h>
#include <mma.h>
#include <cstdint>

using namespace nvcuda;

// Problem constants
#define B_   2
#define T_   4096
#define PD   256
#define E_   512
#define NH   8
#define HD   64
#define H3   1536
#define M_   (B_*T_)   // 8192

// Scratch (static device globals: no allocation allowed)
__device__ float g_x[(size_t)M_*E_];     // 16 MB
__device__ float g_qkv[(size_t)M_*H3];   // 48 MB
__device__ float g_att[(size_t)M_*E_];   // 16 MB

// ---------------------------------------------------------------------------
// Generic TF32 GEMM with bias:  C[M,N] = A[M,K](row) * B[K,N](row) + bias[N]
// (unchanged from R11 — attention is this round's target)
// ---------------------------------------------------------------------------
#define GBM 64
#define GBN 64
#define GBK 16
#define AKP 20
#define BNP 68

#define CVT_FRAG(f) do { _Pragma("unroll") \
    for (int _i = 0; _i < (f).num_elements; _i++) \
        (f).x[_i] = wmma::__float_to_tf32((f).x[_i]); } while (0)

__global__ __launch_bounds__(128) void gemm_bias_kernel(
    const float* __restrict__ A, const float* __restrict__ B,
    const float* __restrict__ bias, float* __restrict__ C,
    int M, int N, int K)
{
    __shared__ __align__(32) float As[GBM][AKP];
    __shared__ __align__(32) float Bs[GBK][BNP];
    __shared__ __align__(32) float Cs[GBM][GBN + 4];

    const int tid  = threadIdx.x;
    const int w    = tid >> 5;
    const int wr   = w >> 1;
    const int wc   = w & 1;
    const int row0 = blockIdx.y * GBM;
    const int col0 = blockIdx.x * GBN;

    wmma::fragment<wmma::accumulator, 16, 16, 8, float> acc[2][2];
#pragma unroll
    for (int i = 0; i < 2; i++)
#pragma unroll
        for (int j = 0; j < 2; j++)
            wmma::fill_fragment(acc[i][j], 0.0f);

    for (int k0 = 0; k0 < K; k0 += GBK) {
#pragma unroll
        for (int e = tid; e < GBM * GBK; e += 128) {
            int r = e >> 4, kk = e & 15;
            As[r][kk] = A[(size_t)(row0 + r) * K + k0 + kk];
        }
#pragma unroll
        for (int e = tid; e < GBK * GBN; e += 128) {
            int kk = e >> 6, n = e & 63;
            Bs[kk][n] = B[(size_t)(k0 + kk) * N + col0 + n];
        }
        __syncthreads();

#pragma unroll
        for (int ks = 0; ks < GBK; ks += 8) {
            wmma::fragment<wmma::matrix_a, 16, 16, 8, wmma::precision::tf32, wmma::row_major> af[2];
            wmma::fragment<wmma::matrix_b, 16, 16, 8, wmma::precision::tf32, wmma::row_major> bf[2];
            wmma::load_matrix_sync(af[0], &As[wr * 32][ks], AKP);
            wmma::load_matrix_sync(af[1], &As[wr * 32 + 16][ks], AKP);
            CVT_FRAG(af[0]); CVT_FRAG(af[1]);
            wmma::load_matrix_sync(bf[0], &Bs[ks][wc * 32], BNP);
            wmma::load_matrix_sync(bf[1], &Bs[ks][wc * 32 + 16], BNP);
            CVT_FRAG(bf[0]); CVT_FRAG(bf[1]);
#pragma unroll
            for (int i = 0; i < 2; i++)
#pragma unroll
                for (int j = 0; j < 2; j++)
                    wmma::mma_sync(acc[i][j], af[i], bf[j], acc[i][j]);
        }
        __syncthreads();
    }

#pragma unroll
    for (int i = 0; i < 2; i++)
#pragma unroll
        for (int j = 0; j < 2; j++)
            wmma::store_matrix_sync(&Cs[wr * 32 + i * 16][wc * 32 + j * 16],
                                    acc[i][j], GBN + 4, wmma::mem_row_major);
    __syncthreads();
#pragma unroll
    for (int e = tid; e < GBM * GBN; e += 128) {
        int r = e >> 6, n = e & 63;
        C[(size_t)(row0 + r) * N + col0 + n] = Cs[r][n] + bias[col0 + n];
    }
}

// ---------------------------------------------------------------------------
// Flash attention v2: register-resident S/O/m/l, raw mma.m16n8k8 tf32.
// Block: 4 warps (128 thr), q-tile 64 (16 rows/warp), kv-tile 64.
// Grid: (T/64, B*NH).
// ---------------------------------------------------------------------------
#define QT2  64
#define KT2  64
#define KLD  68   // K & P lead dim: bank = 4r+j -> conflict-free for row=t/4,col=t%4 pattern
#define VLD  72   // V lead dim:     bank = 8j+r -> conflict-free for row=t%4,col=t/4 pattern
#define PLD  68

#define ATT2_SMEM ((KT2*KLD + KT2*VLD + 4*16*PLD) * 4)   // 53248 B

__device__ __forceinline__ uint32_t f2tf32(float x) {
    uint32_t r;
    asm("cvt.rna.tf32.f32 %0, %1;" : "=r"(r) : "f"(x));
    return r;
}

__device__ __forceinline__ void mma_tf32(float c[4], const uint32_t a[4],
                                         uint32_t b0, uint32_t b1) {
    asm volatile(
        "mma.sync.aligned.m16n8k8.row.col.f32.tf32.tf32.f32 "
        "{%0,%1,%2,%3}, {%4,%5,%6,%7}, {%8,%9}, {%0,%1,%2,%3};"
        : "+f"(c[0]), "+f"(c[1]), "+f"(c[2]), "+f"(c[3])
        : "r"(a[0]), "r"(a[1]), "r"(a[2]), "r"(a[3]), "r"(b0), "r"(b1));
}

__global__ __launch_bounds__(128) void attn2_kernel(
    const float* __restrict__ qkv, float* __restrict__ att)
{
    extern __shared__ __align__(128) float sm2[];
    float* Ks = sm2;                    // KT2 x KLD (tf32 values)
    float* Vs = Ks + KT2 * KLD;         // KT2 x VLD (tf32 values)
    float* Ps = Vs + KT2 * VLD;         // 4 warps x 16 x PLD

    const int tid  = threadIdx.x;
    const int w    = tid >> 5;
    const int lane = tid & 31;
    const int qr   = lane >> 2;   // 0..7
    const int qc   = lane & 3;    // 0..3

    const int bh = blockIdx.y;
    const int b  = bh >> 3;
    const int h  = bh & 7;
    const int q0 = blockIdx.x * QT2;

    const float* qb = qkv + (size_t)b * T_ * H3 + (size_t)h * HD;
    const float* kb = qb + E_;
    const float* vb = qb + 2 * E_;

    // ---- Stage Q (scaled by 1/sqrt(d)) through Ks, build Q fragments ----
#pragma unroll
    for (int e = tid; e < QT2 * HD / 4; e += 128) {
        int r  = e >> 4;
        int c4 = (e & 15) << 2;
        float4 v = *(const float4*)(qb + (size_t)(q0 + r) * H3 + c4);
        v.x *= 0.125f; v.y *= 0.125f; v.z *= 0.125f; v.w *= 0.125f;
        *(float4*)(Ks + r * KLD + c4) = v;
    }
    __syncthreads();

    uint32_t qa[8][4];
    {
        const float* q00 = Ks + (w * 16 + qr) * KLD + qc;
#pragma unroll
        for (int ks = 0; ks < 8; ks++) {
            qa[ks][0] = f2tf32(q00[ks * 8]);
            qa[ks][1] = f2tf32(q00[8 * KLD + ks * 8]);
            qa[ks][2] = f2tf32(q00[ks * 8 + 4]);
            qa[ks][3] = f2tf32(q00[8 * KLD + ks * 8 + 4]);
        }
    }

    float oacc[8][4];
#pragma unroll
    for (int nt = 0; nt < 8; nt++)
#pragma unroll
        for (int i = 0; i < 4; i++) oacc[nt][i] = 0.0f;
    float m0 = -1e30f, m1 = -1e30f, l0 = 0.0f, l1 = 0.0f;

    float* Pw = Ps + w * 16 * PLD;

    for (int kt = 0; kt < T_; kt += KT2) {
        __syncthreads();   // all warps done reading Ks/Vs of previous tile

        // ---- Load K, V tiles (convert to tf32 once, at fill) ----
#pragma unroll
        for (int e = tid; e < KT2 * HD / 4; e += 128) {
            int r  = e >> 4;
            int c4 = (e & 15) << 2;
            const size_t gofs = (size_t)(kt + r) * H3 + c4;
            float4 kv = *(const float4*)(kb + gofs);
            kv.x = __uint_as_float(f2tf32(kv.x));
            kv.y = __uint_as_float(f2tf32(kv.y));
            kv.z = __uint_as_float(f2tf32(kv.z));
            kv.w = __uint_as_float(f2tf32(kv.w));
            *(float4*)(Ks + r * KLD + c4) = kv;
            float4 vv = *(const float4*)(vb + gofs);
            vv.x = __uint_as_float(f2tf32(vv.x));
            vv.y = __uint_as_float(f2tf32(vv.y));
            vv.z = __uint_as_float(f2tf32(vv.z));
            vv.w = __uint_as_float(f2tf32(vv.w));
            *(float4*)(Vs + r * VLD + c4) = vv;
        }
        __syncthreads();

        // ---- S = Q @ K^T (registers) ----
        float sacc[8][4];
#pragma unroll
        for (int nt = 0; nt < 8; nt++) {
            sacc[nt][0] = sacc[nt][1] = sacc[nt][2] = sacc[nt][3] = 0.0f;
            const float* kbase = Ks + (nt * 8 + qr) * KLD + qc;
#pragma unroll
            for (int ks = 0; ks < 8; ks++) {
                uint32_t b0 = __float_as_uint(kbase[ks * 8]);
                uint32_t b1 = __float_as_uint(kbase[ks * 8 + 4]);
                mma_tf32(sacc[nt], qa[ks], b0, b1);
            }
        }

        // ---- Online softmax in registers ----
        float tm0 = -1e30f, tm1 = -1e30f;
#pragma unroll
        for (int nt = 0; nt < 8; nt++) {
            tm0 = fmaxf(tm0, fmaxf(sacc[nt][0], sacc[nt][1]));
            tm1 = fmaxf(tm1, fmaxf(sacc[nt][2], sacc[nt][3]));
        }
        tm0 = fmaxf(tm0, __shfl_xor_sync(0xffffffffu, tm0, 1));
        tm0 = fmaxf(tm0, __shfl_xor_sync(0xffffffffu, tm0, 2));
        tm1 = fmaxf(tm1, __shfl_xor_sync(0xffffffffu, tm1, 1));
        tm1 = fmaxf(tm1, __shfl_xor_sync(0xffffffffu, tm1, 2));

        const float mn0 = fmaxf(m0, tm0);
        const float mn1 = fmaxf(m1, tm1);
        const float al0 = __expf(m0 - mn0);
        const float al1 = __expf(m1 - mn1);
        m0 = mn0; m1 = mn1;

        float s0 = 0.0f, s1 = 0.0f;
#pragma unroll
        for (int nt = 0; nt < 8; nt++) {
            float p0 = __expf(sacc[nt][0] - mn0);
            float p1 = __expf(sacc[nt][1] - mn0);
            float p2 = __expf(sacc[nt][2] - mn1);
            float p3 = __expf(sacc[nt][3] - mn1);
            s0 += p0 + p1;
            s1 += p2 + p3;
            // store P (tf32-rounded) to per-warp smem for PV A-frags
            float* pr = Pw + qr * PLD + nt * 8 + 2 * qc;
            *(float2*)pr = make_float2(__uint_as_float(f2tf32(p0)),
                                       __uint_as_float(f2tf32(p1)));
            *(float2*)(pr + 8 * PLD) = make_float2(__uint_as_float(f2tf32(p2)),
                                                   __uint_as_float(f2tf32(p3)));
        }
        s0 += __shfl_xor_sync(0xffffffffu, s0, 1);
        s0 += __shfl_xor_sync(0xffffffffu, s0, 2);
        s1 += __shfl_xor_sync(0xffffffffu, s1, 1);
        s1 += __shfl_xor_sync(0xffffffffu, s1, 2);
        l0 = l0 * al0 + s0;
        l1 = l1 * al1 + s1;

#pragma unroll
        for (int nt = 0; nt < 8; nt++) {
            oacc[nt][0] *= al0; oacc[nt][1] *= al0;
            oacc[nt][2] *= al1; oacc[nt][3] *= al1;
        }
        __syncwarp();   // P visible to the warp's fragment loads

        // ---- O += P @ V ----
#pragma unroll
        for (int ks = 0; ks < 8; ks++) {
            uint32_t pa[4];
            const float* pb = Pw + qr * PLD + ks * 8 + qc;
            pa[0] = __float_as_uint(pb[0]);
            pa[1] = __float_as_uint(pb[8 * PLD]);
            pa[2] = __float_as_uint(pb[4]);
            pa[3] = __float_as_uint(pb[8 * PLD + 4]);
            const float* vbase = Vs + (ks * 8 + qc) * VLD + qr;
#pragma unroll
            for (int nt = 0; nt < 8; nt++) {
                uint32_t b0 = __float_as_uint(vbase[nt * 8]);
                uint32_t b1 = __float_as_uint(vbase[4 * VLD + nt * 8]);
                mma_tf32(oacc[nt], pa, b0, b1);
            }
        }
    }

    // ---- Normalize and write out ----
    const float inv0 = 1.0f / l0;
    const float inv1 = 1.0f / l1;
    const size_t row0 = (size_t)(b * T_ + q0 + w * 16 + qr);
    float* o0 = att + row0 * E_ + h * HD + 2 * qc;
    float* o1 = o0 + 8 * E_;
#pragma unroll
    for (int nt = 0; nt < 8; nt++) {
        *(float2*)(o0 + nt * 8) = make_float2(oacc[nt][0] * inv0, oacc[nt][1] * inv0);
        *(float2*)(o1 + nt * 8) = make_float2(oacc[nt][2] * inv1, oacc[nt][3] * inv1);
    }
}

// ---------------------------------------------------------------------------
// Launch
// ---------------------------------------------------------------------------
extern "C" void kernel_launch(void* const* d_in, const int* in_sizes, int n_in,
                              void* d_out, int out_size)
{
    const float* prompt = (const float*)d_in[0];
    const float* Wp     = (const float*)d_in[1];
    const float* bp     = (const float*)d_in[2];
    const float* Wqkv   = (const float*)d_in[3];
    const float* bqkv   = (const float*)d_in[4];
    const float* Wo     = (const float*)d_in[5];
    const float* bo     = (const float*)d_in[6];
    float* out = (float*)d_out;

    float *x, *qkv, *att;
    cudaGetSymbolAddress((void**)&x,   g_x);
    cudaGetSymbolAddress((void**)&qkv, g_qkv);
    cudaGetSymbolAddress((void**)&att, g_att);

    cudaFuncSetAttribute(attn2_kernel,
                         cudaFuncAttributeMaxDynamicSharedMemorySize,
                         ATT2_SMEM);

    // 1) x = prompt @ Wp + bp          [8192,256]x[256,512]
    {
        dim3 g(E_ / GBN, M_ / GBM);
        gemm_bias_kernel<<<g, 128>>>(prompt, Wp, bp, x, M_, E_, PD);
    }
    // 2) qkv = x @ Wqkv + bqkv         [8192,512]x[512,1536]
    {
        dim3 g(H3 / GBN, M_ / GBM);
        gemm_bias_kernel<<<g, 128>>>(x, Wqkv, bqkv, qkv, M_, H3, E_);
    }
    // 3) attention (flash v2, register-resident)
    {
        dim3 g(T_ / QT2, B_ * NH);
        attn2_kernel<<<g, 128, ATT2_SMEM>>>(qkv, att);
    }
    // 4) out = att @ Wo + bo           [8192,512]x[512,256]
    {
        dim3 g(PD / GBN, M_ / GBM);
        gemm_bias_kernel<<<g, 128>>>(att, Wo, bo, out, M_, PD, E_);
    }
}

// round 16
// speedup vs baseline: 1.2351x; 1.2351x over previous
#include <cuda_runtime.h>
#include <cuda_bf16.h>
#include <mma.h>
#include <cstdint>

// Problem constants
#define B_   2
#define T_   4096
#define PD   256
#define E_   512
#define NH   8
#define HD   64
#define H3   1536
#define M_   (B_*T_)   // 8192

// Scratch (static device globals: no allocation allowed)
__device__ float g_x[(size_t)M_*E_];     // 16 MB
__device__ float g_qkv[(size_t)M_*H3];   // 48 MB
__device__ float g_att[(size_t)M_*E_];   // 16 MB

__device__ __forceinline__ uint32_t f2tf32(float x) {
    uint32_t r;
    asm("cvt.rna.tf32.f32 %0, %1;" : "=r"(r) : "f"(x));
    return r;
}
__device__ __forceinline__ float f2tf32f(float x) {
    return __uint_as_float(f2tf32(x));
}

__device__ __forceinline__ void mma_tf32(float c[4], const uint32_t a[4],
                                         uint32_t b0, uint32_t b1) {
    asm volatile(
        "mma.sync.aligned.m16n8k8.row.col.f32.tf32.tf32.f32 "
        "{%0,%1,%2,%3}, {%4,%5,%6,%7}, {%8,%9}, {%0,%1,%2,%3};"
        : "+f"(c[0]), "+f"(c[1]), "+f"(c[2]), "+f"(c[3])
        : "r"(a[0]), "r"(a[1]), "r"(a[2]), "r"(a[3]), "r"(b0), "r"(b1));
}

// ---------------------------------------------------------------------------
// TF32 GEMM with bias: C[M,N] = A[M,K] * B[K,N] + bias[N]   (row-major)
// 128x128 block tile, BK=16, 256 threads (8 warps 2x4), warp tile 64x32.
// Double-buffered smem + global->register prefetch. tf32 convert at fill.
// ---------------------------------------------------------------------------
#define TBM 128
#define TBN 128
#define TBK 16
#define TALD 20    // As row stride (floats): banks (20*qr+qc)%32 all distinct
#define TBLD 136   // Bs row stride (floats): banks (8*qc+qr)%32 all distinct

__global__ __launch_bounds__(256) void gemm_bias2_kernel(
    const float* __restrict__ A, const float* __restrict__ B,
    const float* __restrict__ bias, float* __restrict__ C,
    int M, int N, int K)
{
    __shared__ __align__(128) float As[2][TBM][TALD];   // 20.0 KB
    __shared__ __align__(128) float Bs[2][TBK][TBLD];   // 17.0 KB

    const int tid  = threadIdx.x;
    const int w    = tid >> 5;
    const int lane = tid & 31;
    const int qr   = lane >> 2;   // 0..7
    const int qc   = lane & 3;    // 0..3
    const int wm   = w >> 2;      // 0..1
    const int wn   = w & 3;       // 0..3

    const int row0 = blockIdx.y * TBM;
    const int col0 = blockIdx.x * TBN;

    // Global load mapping
    const int tA_r = tid >> 2;          // 0..63  (+64)
    const int tA_c = (tid & 3) << 2;    // 0,4,8,12
    const int tB_r = tid >> 5;          // 0..7   (+8)
    const int tB_c = (tid & 31) << 2;   // 0..124

    const float* Ag0 = A + (size_t)(row0 + tA_r) * K + tA_c;
    const float* Ag1 = Ag0 + (size_t)64 * K;
    const float* Bg0 = B + (size_t)tB_r * N + col0 + tB_c;
    const float* Bg1 = Bg0 + (size_t)8 * N;

    float acc[4][4][4];
#pragma unroll
    for (int mf = 0; mf < 4; mf++)
#pragma unroll
        for (int nf = 0; nf < 4; nf++)
#pragma unroll
            for (int i = 0; i < 4; i++) acc[mf][nf][i] = 0.0f;

    float4 pa0, pa1, pb0, pb1;

    // preload tile 0
    pa0 = *(const float4*)(Ag0);
    pa1 = *(const float4*)(Ag1);
    pb0 = *(const float4*)(Bg0);
    pb1 = *(const float4*)(Bg1);

    // store tile 0 -> buf 0 (tf32 convert at fill)
    {
        float4 t;
        t.x=f2tf32f(pa0.x); t.y=f2tf32f(pa0.y); t.z=f2tf32f(pa0.z); t.w=f2tf32f(pa0.w);
        *(float4*)&As[0][tA_r][tA_c] = t;
        t.x=f2tf32f(pa1.x); t.y=f2tf32f(pa1.y); t.z=f2tf32f(pa1.z); t.w=f2tf32f(pa1.w);
        *(float4*)&As[0][tA_r + 64][tA_c] = t;
        t.x=f2tf32f(pb0.x); t.y=f2tf32f(pb0.y); t.z=f2tf32f(pb0.z); t.w=f2tf32f(pb0.w);
        *(float4*)&Bs[0][tB_r][tB_c] = t;
        t.x=f2tf32f(pb1.x); t.y=f2tf32f(pb1.y); t.z=f2tf32f(pb1.z); t.w=f2tf32f(pb1.w);
        *(float4*)&Bs[0][tB_r + 8][tB_c] = t;
    }
    __syncthreads();

    const int niter = K / TBK;
    for (int it = 0; it < niter; it++) {
        const int buf = it & 1;
        const bool more = (it + 1) < niter;

        // prefetch next tile into registers
        if (more) {
            const int k0 = (it + 1) * TBK;
            pa0 = *(const float4*)(Ag0 + k0);
            pa1 = *(const float4*)(Ag1 + k0);
            pb0 = *(const float4*)(Bg0 + (size_t)k0 * N);
            pb1 = *(const float4*)(Bg1 + (size_t)k0 * N);
        }

        // compute current tile
#pragma unroll
        for (int ks = 0; ks < TBK; ks += 8) {
            uint32_t af[4][4];
#pragma unroll
            for (int mf = 0; mf < 4; mf++) {
                const float* ab = &As[buf][wm * 64 + mf * 16 + qr][ks + qc];
                af[mf][0] = __float_as_uint(ab[0]);
                af[mf][1] = __float_as_uint(ab[8 * TALD]);
                af[mf][2] = __float_as_uint(ab[4]);
                af[mf][3] = __float_as_uint(ab[8 * TALD + 4]);
            }
            uint32_t bf[4][2];
#pragma unroll
            for (int nf = 0; nf < 4; nf++) {
                const float* bb = &Bs[buf][ks + qc][wn * 32 + nf * 8 + qr];
                bf[nf][0] = __float_as_uint(bb[0]);
                bf[nf][1] = __float_as_uint(bb[4 * TBLD]);
            }
#pragma unroll
            for (int mf = 0; mf < 4; mf++)
#pragma unroll
                for (int nf = 0; nf < 4; nf++)
                    mma_tf32(acc[mf][nf], af[mf], bf[nf][0], bf[nf][1]);
        }

        // store prefetched tile into other buffer
        if (more) {
            const int nb = buf ^ 1;
            float4 t;
            t.x=f2tf32f(pa0.x); t.y=f2tf32f(pa0.y); t.z=f2tf32f(pa0.z); t.w=f2tf32f(pa0.w);
            *(float4*)&As[nb][tA_r][tA_c] = t;
            t.x=f2tf32f(pa1.x); t.y=f2tf32f(pa1.y); t.z=f2tf32f(pa1.z); t.w=f2tf32f(pa1.w);
            *(float4*)&As[nb][tA_r + 64][tA_c] = t;
            t.x=f2tf32f(pb0.x); t.y=f2tf32f(pb0.y); t.z=f2tf32f(pb0.z); t.w=f2tf32f(pb0.w);
            *(float4*)&Bs[nb][tB_r][tB_c] = t;
            t.x=f2tf32f(pb1.x); t.y=f2tf32f(pb1.y); t.z=f2tf32f(pb1.z); t.w=f2tf32f(pb1.w);
            *(float4*)&Bs[nb][tB_r + 8][tB_c] = t;
            __syncthreads();
        }
    }

    // Epilogue: registers -> global with bias (float2, full 32B sectors)
#pragma unroll
    for (int mf = 0; mf < 4; mf++) {
        const int m = row0 + wm * 64 + mf * 16 + qr;
        float* c0 = C + (size_t)m * N;
        float* c1 = c0 + (size_t)8 * N;
#pragma unroll
        for (int nf = 0; nf < 4; nf++) {
            const int n = col0 + wn * 32 + nf * 8 + 2 * qc;
            const float b0 = bias[n], b1 = bias[n + 1];
            *(float2*)(c0 + n) = make_float2(acc[mf][nf][0] + b0, acc[mf][nf][1] + b1);
            *(float2*)(c1 + n) = make_float2(acc[mf][nf][2] + b0, acc[mf][nf][3] + b1);
        }
    }
}

// ---------------------------------------------------------------------------
// Flash attention v2 (unchanged from R15): register-resident S/O/m/l.
// ---------------------------------------------------------------------------
#define QT2  64
#define KT2  64
#define KLD  68
#define VLD  72
#define PLD  68

#define ATT2_SMEM ((KT2*KLD + KT2*VLD + 4*16*PLD) * 4)   // 53248 B

__global__ __launch_bounds__(128) void attn2_kernel(
    const float* __restrict__ qkv, float* __restrict__ att)
{
    extern __shared__ __align__(128) float sm2[];
    float* Ks = sm2;
    float* Vs = Ks + KT2 * KLD;
    float* Ps = Vs + KT2 * VLD;

    const int tid  = threadIdx.x;
    const int w    = tid >> 5;
    const int lane = tid & 31;
    const int qr   = lane >> 2;
    const int qc   = lane & 3;

    const int bh = blockIdx.y;
    const int b  = bh >> 3;
    const int h  = bh & 7;
    const int q0 = blockIdx.x * QT2;

    const float* qb = qkv + (size_t)b * T_ * H3 + (size_t)h * HD;
    const float* kb = qb + E_;
    const float* vb = qb + 2 * E_;

#pragma unroll
    for (int e = tid; e < QT2 * HD / 4; e += 128) {
        int r  = e >> 4;
        int c4 = (e & 15) << 2;
        float4 v = *(const float4*)(qb + (size_t)(q0 + r) * H3 + c4);
        v.x *= 0.125f; v.y *= 0.125f; v.z *= 0.125f; v.w *= 0.125f;
        *(float4*)(Ks + r * KLD + c4) = v;
    }
    __syncthreads();

    uint32_t qa[8][4];
    {
        const float* q00 = Ks + (w * 16 + qr) * KLD + qc;
#pragma unroll
        for (int ks = 0; ks < 8; ks++) {
            qa[ks][0] = f2tf32(q00[ks * 8]);
            qa[ks][1] = f2tf32(q00[8 * KLD + ks * 8]);
            qa[ks][2] = f2tf32(q00[ks * 8 + 4]);
            qa[ks][3] = f2tf32(q00[8 * KLD + ks * 8 + 4]);
        }
    }

    float oacc[8][4];
#pragma unroll
    for (int nt = 0; nt < 8; nt++)
#pragma unroll
        for (int i = 0; i < 4; i++) oacc[nt][i] = 0.0f;
    float m0 = -1e30f, m1 = -1e30f, l0 = 0.0f, l1 = 0.0f;

    float* Pw = Ps + w * 16 * PLD;

    for (int kt = 0; kt < T_; kt += KT2) {
        __syncthreads();

#pragma unroll
        for (int e = tid; e < KT2 * HD / 4; e += 128) {
            int r  = e >> 4;
            int c4 = (e & 15) << 2;
            const size_t gofs = (size_t)(kt + r) * H3 + c4;
            float4 kv = *(const float4*)(kb + gofs);
            kv.x = f2tf32f(kv.x); kv.y = f2tf32f(kv.y);
            kv.z = f2tf32f(kv.z); kv.w = f2tf32f(kv.w);
            *(float4*)(Ks + r * KLD + c4) = kv;
            float4 vv = *(const float4*)(vb + gofs);
            vv.x = f2tf32f(vv.x); vv.y = f2tf32f(vv.y);
            vv.z = f2tf32f(vv.z); vv.w = f2tf32f(vv.w);
            *(float4*)(Vs + r * VLD + c4) = vv;
        }
        __syncthreads();

        float sacc[8][4];
#pragma unroll
        for (int nt = 0; nt < 8; nt++) {
            sacc[nt][0] = sacc[nt][1] = sacc[nt][2] = sacc[nt][3] = 0.0f;
            const float* kbase = Ks + (nt * 8 + qr) * KLD + qc;
#pragma unroll
            for (int ks = 0; ks < 8; ks++) {
                uint32_t b0 = __float_as_uint(kbase[ks * 8]);
                uint32_t b1 = __float_as_uint(kbase[ks * 8 + 4]);
                mma_tf32(sacc[nt], qa[ks], b0, b1);
            }
        }

        float tm0 = -1e30f, tm1 = -1e30f;
#pragma unroll
        for (int nt = 0; nt < 8; nt++) {
            tm0 = fmaxf(tm0, fmaxf(sacc[nt][0], sacc[nt][1]));
            tm1 = fmaxf(tm1, fmaxf(sacc[nt][2], sacc[nt][3]));
        }
        tm0 = fmaxf(tm0, __shfl_xor_sync(0xffffffffu, tm0, 1));
        tm0 = fmaxf(tm0, __shfl_xor_sync(0xffffffffu, tm0, 2));
        tm1 = fmaxf(tm1, __shfl_xor_sync(0xffffffffu, tm1, 1));
        tm1 = fmaxf(tm1, __shfl_xor_sync(0xffffffffu, tm1, 2));

        const float mn0 = fmaxf(m0, tm0);
        const float mn1 = fmaxf(m1, tm1);
        const float al0 = __expf(m0 - mn0);
        const float al1 = __expf(m1 - mn1);
        m0 = mn0; m1 = mn1;

        float s0 = 0.0f, s1 = 0.0f;
#pragma unroll
        for (int nt = 0; nt < 8; nt++) {
            float p0 = __expf(sacc[nt][0] - mn0);
            float p1 = __expf(sacc[nt][1] - mn0);
            float p2 = __expf(sacc[nt][2] - mn1);
            float p3 = __expf(sacc[nt][3] - mn1);
            s0 += p0 + p1;
            s1 += p2 + p3;
            float* pr = Pw + qr * PLD + nt * 8 + 2 * qc;
            *(float2*)pr = make_float2(f2tf32f(p0), f2tf32f(p1));
            *(float2*)(pr + 8 * PLD) = make_float2(f2tf32f(p2), f2tf32f(p3));
        }
        s0 += __shfl_xor_sync(0xffffffffu, s0, 1);
        s0 += __shfl_xor_sync(0xffffffffu, s0, 2);
        s1 += __shfl_xor_sync(0xffffffffu, s1, 1);
        s1 += __shfl_xor_sync(0xffffffffu, s1, 2);
        l0 = l0 * al0 + s0;
        l1 = l1 * al1 + s1;

#pragma unroll
        for (int nt = 0; nt < 8; nt++) {
            oacc[nt][0] *= al0; oacc[nt][1] *= al0;
            oacc[nt][2] *= al1; oacc[nt][3] *= al1;
        }
        __syncwarp();

#pragma unroll
        for (int ks = 0; ks < 8; ks++) {
            uint32_t pa[4];
            const float* pb = Pw + qr * PLD + ks * 8 + qc;
            pa[0] = __float_as_uint(pb[0]);
            pa[1] = __float_as_uint(pb[8 * PLD]);
            pa[2] = __float_as_uint(pb[4]);
            pa[3] = __float_as_uint(pb[8 * PLD + 4]);
            const float* vbase = Vs + (ks * 8 + qc) * VLD + qr;
#pragma unroll
            for (int nt = 0; nt < 8; nt++) {
                uint32_t b0 = __float_as_uint(vbase[nt * 8]);
                uint32_t b1 = __float_as_uint(vbase[4 * VLD + nt * 8]);
                mma_tf32(oacc[nt], pa, b0, b1);
            }
        }
    }

    const float inv0 = 1.0f / l0;
    const float inv1 = 1.0f / l1;
    const size_t row0 = (size_t)(b * T_ + q0 + w * 16 + qr);
    float* o0 = att + row0 * E_ + h * HD + 2 * qc;
    float* o1 = o0 + 8 * E_;
#pragma unroll
    for (int nt = 0; nt < 8; nt++) {
        *(float2*)(o0 + nt * 8) = make_float2(oacc[nt][0] * inv0, oacc[nt][1] * inv0);
        *(float2*)(o1 + nt * 8) = make_float2(oacc[nt][2] * inv1, oacc[nt][3] * inv1);
    }
}

// ---------------------------------------------------------------------------
// Launch
// ---------------------------------------------------------------------------
extern "C" void kernel_launch(void* const* d_in, const int* in_sizes, int n_in,
                              void* d_out, int out_size)
{
    const float* prompt = (const float*)d_in[0];
    const float* Wp     = (const float*)d_in[1];
    const float* bp     = (const float*)d_in[2];
    const float* Wqkv   = (const float*)d_in[3];
    const float* bqkv   = (const float*)d_in[4];
    const float* Wo     = (const float*)d_in[5];
    const float* bo     = (const float*)d_in[6];
    float* out = (float*)d_out;

    float *x, *qkv, *att;
    cudaGetSymbolAddress((void**)&x,   g_x);
    cudaGetSymbolAddress((void**)&qkv, g_qkv);
    cudaGetSymbolAddress((void**)&att, g_att);

    cudaFuncSetAttribute(attn2_kernel,
                         cudaFuncAttributeMaxDynamicSharedMemorySize,
                         ATT2_SMEM);

    // 1) x = prompt @ Wp + bp          [8192,256]x[256,512]
    {
        dim3 g(E_ / TBN, M_ / TBM);
        gemm_bias2_kernel<<<g, 256>>>(prompt, Wp, bp, x, M_, E_, PD);
    }
    // 2) qkv = x @ Wqkv + bqkv         [8192,512]x[512,1536]
    {
        dim3 g(H3 / TBN, M_ / TBM);
        gemm_bias2_kernel<<<g, 256>>>(x, Wqkv, bqkv, qkv, M_, H3, E_);
    }
    // 3) attention (flash v2, register-resident)
    {
        dim3 g(T_ / QT2, B_ * NH);
        attn2_kernel<<<g, 128, ATT2_SMEM>>>(qkv, att);
    }
    // 4) out = att @ Wo + bo           [8192,512]x[512,256]
    {
        dim3 g(PD / TBN, M_ / TBM);
        gemm_bias2_kernel<<<g, 256>>>(att, Wo, bo, out, M_, PD, E_);
    }
}

// round 17
// speedup vs baseline: 1.3058x; 1.0572x over previous
#include <cuda_runtime.h>
#include <cuda_bf16.h>
#include <mma.h>
#include <cstdint>

// Problem constants
#define B_   2
#define T_   4096
#define PD   256
#define E_   512
#define NH   8
#define HD   64
#define H3   1536
#define M_   (B_*T_)   // 8192

// Scratch (static device globals: no allocation allowed)
__device__ float g_x[(size_t)M_*E_];     // 16 MB
__device__ float g_qkv[(size_t)M_*H3];   // 48 MB
__device__ float g_att[(size_t)M_*E_];   // 16 MB

__device__ __forceinline__ uint32_t f2tf32(float x) {
    uint32_t r;
    asm("cvt.rna.tf32.f32 %0, %1;" : "=r"(r) : "f"(x));
    return r;
}
__device__ __forceinline__ float f2tf32f(float x) {
    return __uint_as_float(f2tf32(x));
}
__device__ __forceinline__ float ex2(float x) {
    float r;
    asm("ex2.approx.f32 %0, %1;" : "=f"(r) : "f"(x));
    return r;
}

__device__ __forceinline__ void mma_tf32(float c[4], const uint32_t a[4],
                                         uint32_t b0, uint32_t b1) {
    asm volatile(
        "mma.sync.aligned.m16n8k8.row.col.f32.tf32.tf32.f32 "
        "{%0,%1,%2,%3}, {%4,%5,%6,%7}, {%8,%9}, {%0,%1,%2,%3};"
        : "+f"(c[0]), "+f"(c[1]), "+f"(c[2]), "+f"(c[3])
        : "r"(a[0]), "r"(a[1]), "r"(a[2]), "r"(a[3]), "r"(b0), "r"(b1));
}

// ---------------------------------------------------------------------------
// TF32 GEMM with bias (unchanged from R16)
// ---------------------------------------------------------------------------
#define TBM 128
#define TBN 128
#define TBK 16
#define TALD 20
#define TBLD 136

__global__ __launch_bounds__(256) void gemm_bias2_kernel(
    const float* __restrict__ A, const float* __restrict__ B,
    const float* __restrict__ bias, float* __restrict__ C,
    int M, int N, int K)
{
    __shared__ __align__(128) float As[2][TBM][TALD];
    __shared__ __align__(128) float Bs[2][TBK][TBLD];

    const int tid  = threadIdx.x;
    const int w    = tid >> 5;
    const int lane = tid & 31;
    const int qr   = lane >> 2;
    const int qc   = lane & 3;
    const int wm   = w >> 2;
    const int wn   = w & 3;

    const int row0 = blockIdx.y * TBM;
    const int col0 = blockIdx.x * TBN;

    const int tA_r = tid >> 2;
    const int tA_c = (tid & 3) << 2;
    const int tB_r = tid >> 5;
    const int tB_c = (tid & 31) << 2;

    const float* Ag0 = A + (size_t)(row0 + tA_r) * K + tA_c;
    const float* Ag1 = Ag0 + (size_t)64 * K;
    const float* Bg0 = B + (size_t)tB_r * N + col0 + tB_c;
    const float* Bg1 = Bg0 + (size_t)8 * N;

    float acc[4][4][4];
#pragma unroll
    for (int mf = 0; mf < 4; mf++)
#pragma unroll
        for (int nf = 0; nf < 4; nf++)
#pragma unroll
            for (int i = 0; i < 4; i++) acc[mf][nf][i] = 0.0f;

    float4 pa0, pa1, pb0, pb1;

    pa0 = *(const float4*)(Ag0);
    pa1 = *(const float4*)(Ag1);
    pb0 = *(const float4*)(Bg0);
    pb1 = *(const float4*)(Bg1);

    {
        float4 t;
        t.x=f2tf32f(pa0.x); t.y=f2tf32f(pa0.y); t.z=f2tf32f(pa0.z); t.w=f2tf32f(pa0.w);
        *(float4*)&As[0][tA_r][tA_c] = t;
        t.x=f2tf32f(pa1.x); t.y=f2tf32f(pa1.y); t.z=f2tf32f(pa1.z); t.w=f2tf32f(pa1.w);
        *(float4*)&As[0][tA_r + 64][tA_c] = t;
        t.x=f2tf32f(pb0.x); t.y=f2tf32f(pb0.y); t.z=f2tf32f(pb0.z); t.w=f2tf32f(pb0.w);
        *(float4*)&Bs[0][tB_r][tB_c] = t;
        t.x=f2tf32f(pb1.x); t.y=f2tf32f(pb1.y); t.z=f2tf32f(pb1.z); t.w=f2tf32f(pb1.w);
        *(float4*)&Bs[0][tB_r + 8][tB_c] = t;
    }
    __syncthreads();

    const int niter = K / TBK;
    for (int it = 0; it < niter; it++) {
        const int buf = it & 1;
        const bool more = (it + 1) < niter;

        if (more) {
            const int k0 = (it + 1) * TBK;
            pa0 = *(const float4*)(Ag0 + k0);
            pa1 = *(const float4*)(Ag1 + k0);
            pb0 = *(const float4*)(Bg0 + (size_t)k0 * N);
            pb1 = *(const float4*)(Bg1 + (size_t)k0 * N);
        }

#pragma unroll
        for (int ks = 0; ks < TBK; ks += 8) {
            uint32_t af[4][4];
#pragma unroll
            for (int mf = 0; mf < 4; mf++) {
                const float* ab = &As[buf][wm * 64 + mf * 16 + qr][ks + qc];
                af[mf][0] = __float_as_uint(ab[0]);
                af[mf][1] = __float_as_uint(ab[8 * TALD]);
                af[mf][2] = __float_as_uint(ab[4]);
                af[mf][3] = __float_as_uint(ab[8 * TALD + 4]);
            }
            uint32_t bf[4][2];
#pragma unroll
            for (int nf = 0; nf < 4; nf++) {
                const float* bb = &Bs[buf][ks + qc][wn * 32 + nf * 8 + qr];
                bf[nf][0] = __float_as_uint(bb[0]);
                bf[nf][1] = __float_as_uint(bb[4 * TBLD]);
            }
#pragma unroll
            for (int mf = 0; mf < 4; mf++)
#pragma unroll
                for (int nf = 0; nf < 4; nf++)
                    mma_tf32(acc[mf][nf], af[mf], bf[nf][0], bf[nf][1]);
        }

        if (more) {
            const int nb = buf ^ 1;
            float4 t;
            t.x=f2tf32f(pa0.x); t.y=f2tf32f(pa0.y); t.z=f2tf32f(pa0.z); t.w=f2tf32f(pa0.w);
            *(float4*)&As[nb][tA_r][tA_c] = t;
            t.x=f2tf32f(pa1.x); t.y=f2tf32f(pa1.y); t.z=f2tf32f(pa1.z); t.w=f2tf32f(pa1.w);
            *(float4*)&As[nb][tA_r + 64][tA_c] = t;
            t.x=f2tf32f(pb0.x); t.y=f2tf32f(pb0.y); t.z=f2tf32f(pb0.z); t.w=f2tf32f(pb0.w);
            *(float4*)&Bs[nb][tB_r][tB_c] = t;
            t.x=f2tf32f(pb1.x); t.y=f2tf32f(pb1.y); t.z=f2tf32f(pb1.z); t.w=f2tf32f(pb1.w);
            *(float4*)&Bs[nb][tB_r + 8][tB_c] = t;
            __syncthreads();
        }
    }

#pragma unroll
    for (int mf = 0; mf < 4; mf++) {
        const int m = row0 + wm * 64 + mf * 16 + qr;
        float* c0 = C + (size_t)m * N;
        float* c1 = c0 + (size_t)8 * N;
#pragma unroll
        for (int nf = 0; nf < 4; nf++) {
            const int n = col0 + wn * 32 + nf * 8 + 2 * qc;
            const float b0 = bias[n], b1 = bias[n + 1];
            *(float2*)(c0 + n) = make_float2(acc[mf][nf][0] + b0, acc[mf][nf][1] + b1);
            *(float2*)(c1 + n) = make_float2(acc[mf][nf][2] + b0, acc[mf][nf][3] + b1);
        }
    }
}

// ---------------------------------------------------------------------------
// Flash attention v3: 32 q-rows per warp (2 A-frags) -> K/V smem reads per
// unit work halved. Base-2 online softmax (ex2.approx). QT=128, KT=64.
// Block: 4 warps. Grid: (T/128, B*NH).
// ---------------------------------------------------------------------------
#define QT3  128
#define KT3  64
#define KLD  68   // bank(4r+j) distinct
#define VLD  72   // bank(8j+r) distinct
#define PLD  68

#define ATT3_SMEM ((KT3*KLD + KT3*VLD + QT3*PLD) * 4)   // 70656 B

__global__ __launch_bounds__(128, 2) void attn3_kernel(
    const float* __restrict__ qkv, float* __restrict__ att)
{
    extern __shared__ __align__(128) float sm3[];
    float* Ks = sm3;                    // KT3 x KLD
    float* Vs = Ks + KT3 * KLD;         // KT3 x VLD
    float* Ps = Vs + KT3 * VLD;         // QT3 x PLD (Q staging, then P per warp)

    const int tid  = threadIdx.x;
    const int w    = tid >> 5;
    const int lane = tid & 31;
    const int qr   = lane >> 2;   // 0..7
    const int qc   = lane & 3;    // 0..3

    const int bh = blockIdx.y;
    const int b  = bh >> 3;
    const int h  = bh & 7;
    const int q0 = blockIdx.x * QT3;

    const float* qb = qkv + (size_t)b * T_ * H3 + (size_t)h * HD;
    const float* kb = qb + E_;
    const float* vb = qb + 2 * E_;

    // ---- Stage Q (scaled by log2(e)/sqrt(d)) into Ps ----
    const float QSCALE = 0.18033688011112042f;   // 0.125 * log2(e)
#pragma unroll
    for (int e = tid; e < QT3 * HD / 4; e += 128) {
        int r  = e >> 4;
        int c4 = (e & 15) << 2;
        float4 v = *(const float4*)(qb + (size_t)(q0 + r) * H3 + c4);
        v.x *= QSCALE; v.y *= QSCALE; v.z *= QSCALE; v.w *= QSCALE;
        *(float4*)(Ps + r * PLD + c4) = v;
    }
    __syncthreads();

    float* Pw = Ps + (w * 32) * PLD;   // this warp's 32 rows

    // ---- Build Q fragments (2 row-blocks of 16) ----
    uint32_t qa[2][8][4];
#pragma unroll
    for (int mf = 0; mf < 2; mf++) {
        const float* q00 = Pw + (mf * 16 + qr) * PLD + qc;
#pragma unroll
        for (int ks = 0; ks < 8; ks++) {
            qa[mf][ks][0] = f2tf32(q00[ks * 8]);
            qa[mf][ks][1] = f2tf32(q00[8 * PLD + ks * 8]);
            qa[mf][ks][2] = f2tf32(q00[ks * 8 + 4]);
            qa[mf][ks][3] = f2tf32(q00[8 * PLD + ks * 8 + 4]);
        }
    }

    float oacc[2][8][4];
#pragma unroll
    for (int mf = 0; mf < 2; mf++)
#pragma unroll
        for (int nt = 0; nt < 8; nt++)
#pragma unroll
            for (int i = 0; i < 4; i++) oacc[mf][nt][i] = 0.0f;
    float mrow[2][2] = {{-1e30f, -1e30f}, {-1e30f, -1e30f}};
    float lrow[2][2] = {{0.0f, 0.0f}, {0.0f, 0.0f}};

    for (int kt = 0; kt < T_; kt += KT3) {
        __syncthreads();   // everyone done with previous Ks/Vs/Ps

        // ---- Fill K/V tiles (tf32 at fill) ----
#pragma unroll
        for (int e = tid; e < KT3 * HD / 4; e += 128) {
            int r  = e >> 4;
            int c4 = (e & 15) << 2;
            const size_t gofs = (size_t)(kt + r) * H3 + c4;
            float4 kv = *(const float4*)(kb + gofs);
            kv.x = f2tf32f(kv.x); kv.y = f2tf32f(kv.y);
            kv.z = f2tf32f(kv.z); kv.w = f2tf32f(kv.w);
            *(float4*)(Ks + r * KLD + c4) = kv;
            float4 vv = *(const float4*)(vb + gofs);
            vv.x = f2tf32f(vv.x); vv.y = f2tf32f(vv.y);
            vv.z = f2tf32f(vv.z); vv.w = f2tf32f(vv.w);
            *(float4*)(Vs + r * VLD + c4) = vv;
        }
        __syncthreads();

        // ---- S = Q @ K^T : 32 rows x 64 keys per warp ----
        float sacc[2][8][4];
#pragma unroll
        for (int nt = 0; nt < 8; nt++) {
            sacc[0][nt][0] = sacc[0][nt][1] = sacc[0][nt][2] = sacc[0][nt][3] = 0.0f;
            sacc[1][nt][0] = sacc[1][nt][1] = sacc[1][nt][2] = sacc[1][nt][3] = 0.0f;
            const float* kbase = Ks + (nt * 8 + qr) * KLD + qc;
#pragma unroll
            for (int ks = 0; ks < 8; ks++) {
                uint32_t b0 = __float_as_uint(kbase[ks * 8]);
                uint32_t b1 = __float_as_uint(kbase[ks * 8 + 4]);
                mma_tf32(sacc[0][nt], qa[0][ks], b0, b1);
                mma_tf32(sacc[1][nt], qa[1][ks], b0, b1);
            }
        }

        // ---- Base-2 online softmax, P -> smem ----
#pragma unroll
        for (int mf = 0; mf < 2; mf++) {
            float tm0 = -1e30f, tm1 = -1e30f;
#pragma unroll
            for (int nt = 0; nt < 8; nt++) {
                tm0 = fmaxf(tm0, fmaxf(sacc[mf][nt][0], sacc[mf][nt][1]));
                tm1 = fmaxf(tm1, fmaxf(sacc[mf][nt][2], sacc[mf][nt][3]));
            }
            tm0 = fmaxf(tm0, __shfl_xor_sync(0xffffffffu, tm0, 1));
            tm0 = fmaxf(tm0, __shfl_xor_sync(0xffffffffu, tm0, 2));
            tm1 = fmaxf(tm1, __shfl_xor_sync(0xffffffffu, tm1, 1));
            tm1 = fmaxf(tm1, __shfl_xor_sync(0xffffffffu, tm1, 2));

            const float mn0 = fmaxf(mrow[mf][0], tm0);
            const float mn1 = fmaxf(mrow[mf][1], tm1);
            const float al0 = ex2(mrow[mf][0] - mn0);
            const float al1 = ex2(mrow[mf][1] - mn1);
            mrow[mf][0] = mn0; mrow[mf][1] = mn1;

            float s0 = 0.0f, s1 = 0.0f;
#pragma unroll
            for (int nt = 0; nt < 8; nt++) {
                float p0 = ex2(sacc[mf][nt][0] - mn0);
                float p1 = ex2(sacc[mf][nt][1] - mn0);
                float p2 = ex2(sacc[mf][nt][2] - mn1);
                float p3 = ex2(sacc[mf][nt][3] - mn1);
                s0 += p0 + p1;
                s1 += p2 + p3;
                float* pr = Pw + (mf * 16 + qr) * PLD + nt * 8 + 2 * qc;
                *(float2*)pr = make_float2(f2tf32f(p0), f2tf32f(p1));
                *(float2*)(pr + 8 * PLD) = make_float2(f2tf32f(p2), f2tf32f(p3));
            }
            s0 += __shfl_xor_sync(0xffffffffu, s0, 1);
            s0 += __shfl_xor_sync(0xffffffffu, s0, 2);
            s1 += __shfl_xor_sync(0xffffffffu, s1, 1);
            s1 += __shfl_xor_sync(0xffffffffu, s1, 2);
            lrow[mf][0] = lrow[mf][0] * al0 + s0;
            lrow[mf][1] = lrow[mf][1] * al1 + s1;

#pragma unroll
            for (int nt = 0; nt < 8; nt++) {
                oacc[mf][nt][0] *= al0; oacc[mf][nt][1] *= al0;
                oacc[mf][nt][2] *= al1; oacc[mf][nt][3] *= al1;
            }
        }
        __syncwarp();

        // ---- O += P @ V ----
#pragma unroll
        for (int ks = 0; ks < 8; ks++) {
            uint32_t pa0[4], pa1[4];
            const float* pb = Pw + qr * PLD + ks * 8 + qc;
            pa0[0] = __float_as_uint(pb[0]);
            pa0[1] = __float_as_uint(pb[8 * PLD]);
            pa0[2] = __float_as_uint(pb[4]);
            pa0[3] = __float_as_uint(pb[8 * PLD + 4]);
            const float* pb1 = pb + 16 * PLD;
            pa1[0] = __float_as_uint(pb1[0]);
            pa1[1] = __float_as_uint(pb1[8 * PLD]);
            pa1[2] = __float_as_uint(pb1[4]);
            pa1[3] = __float_as_uint(pb1[8 * PLD + 4]);
            const float* vbase = Vs + (ks * 8 + qc) * VLD + qr;
#pragma unroll
            for (int nt = 0; nt < 8; nt++) {
                uint32_t b0 = __float_as_uint(vbase[nt * 8]);
                uint32_t b1 = __float_as_uint(vbase[4 * VLD + nt * 8]);
                mma_tf32(oacc[0][nt], pa0, b0, b1);
                mma_tf32(oacc[1][nt], pa1, b0, b1);
            }
        }
    }

    // ---- Normalize and write out ----
#pragma unroll
    for (int mf = 0; mf < 2; mf++) {
        const float inv0 = 1.0f / lrow[mf][0];
        const float inv1 = 1.0f / lrow[mf][1];
        const size_t row0 = (size_t)(b * T_ + q0 + w * 32 + mf * 16 + qr);
        float* o0 = att + row0 * E_ + h * HD + 2 * qc;
        float* o1 = o0 + 8 * E_;
#pragma unroll
        for (int nt = 0; nt < 8; nt++) {
            *(float2*)(o0 + nt * 8) = make_float2(oacc[mf][nt][0] * inv0,
                                                  oacc[mf][nt][1] * inv0);
            *(float2*)(o1 + nt * 8) = make_float2(oacc[mf][nt][2] * inv1,
                                                  oacc[mf][nt][3] * inv1);
        }
    }
}

// ---------------------------------------------------------------------------
// Launch
// ---------------------------------------------------------------------------
extern "C" void kernel_launch(void* const* d_in, const int* in_sizes, int n_in,
                              void* d_out, int out_size)
{
    const float* prompt = (const float*)d_in[0];
    const float* Wp     = (const float*)d_in[1];
    const float* bp     = (const float*)d_in[2];
    const float* Wqkv   = (const float*)d_in[3];
    const float* bqkv   = (const float*)d_in[4];
    const float* Wo     = (const float*)d_in[5];
    const float* bo     = (const float*)d_in[6];
    float* out = (float*)d_out;

    float *x, *qkv, *att;
    cudaGetSymbolAddress((void**)&x,   g_x);
    cudaGetSymbolAddress((void**)&qkv, g_qkv);
    cudaGetSymbolAddress((void**)&att, g_att);

    cudaFuncSetAttribute(attn3_kernel,
                         cudaFuncAttributeMaxDynamicSharedMemorySize,
                         ATT3_SMEM);

    // 1) x = prompt @ Wp + bp
    {
        dim3 g(E_ / TBN, M_ / TBM);
        gemm_bias2_kernel<<<g, 256>>>(prompt, Wp, bp, x, M_, E_, PD);
    }
    // 2) qkv = x @ Wqkv + bqkv
    {
        dim3 g(H3 / TBN, M_ / TBM);
        gemm_bias2_kernel<<<g, 256>>>(x, Wqkv, bqkv, qkv, M_, H3, E_);
    }
    // 3) attention (flash v3, 32 rows/warp)
    {
        dim3 g(T_ / QT3, B_ * NH);
        attn3_kernel<<<g, 128, ATT3_SMEM>>>(qkv, att);
    }
    // 4) out = att @ Wo + bo
    {
        dim3 g(PD / TBN, M_ / TBM);
        gemm_bias2_kernel<<<g, 256>>>(att, Wo, bo, out, M_, PD, E_);
    }
}